// round 9
// baseline (speedup 1.0000x reference)
#include <cuda_runtime.h>
#include <cstdint>

// Problem constants
#define TT   100
#define BB   256
#define NIN  1024
#define NHID 4096
#define NOUT 512

#define BETA   0.95f
#define THRESH 1.0f

// Confirmed reference arithmetic: cuBLASLt serial split-K.
// GEMM1 (per-step 256x4096x1024): S=2.  GEMM2 (256x512x4096): S=16.
#define SPLIT1 2
#define SPLIT2 16

// Scratch (allocation-free rule: __device__ globals)
__device__ float g_spk1[(size_t)TT * BB * NHID];        // 419 MB
// Partial buffer: 2*M*NHID == 16*M*NOUT == 209,715,200 floats (839 MB)
__device__ float g_part[(size_t)16 * TT * BB * NOUT];

// ---------------------------------------------------------------------------
// Partial SGEMM (NT): Part[s][M][N] = A[M, ks..ks+Kc) @ B[N, ks..ks+Kc)^T
// BM=256 x BN=128 tile, BK=16, 256 threads, 16x8 micro-tile per thread.
// Double-buffered smem tiles + register-staged global loads + DOUBLE-BUFFERED
// REGISTER FRAGMENTS (LDS for step k+1 issued under step k's FFMAs).
// NUMERICS: per output element, a single fp32 accumulator folded by an
// ascending-k FFMA chain starting from 0 — FFMA order identical to the
// passing kernel (only load scheduling changed).
// ---------------------------------------------------------------------------
#define BM 256
#define BN 128
#define BK 16
#define LDA (BM + 4)
#define LDB (BN + 4)
#define GEMM_SMEM ((size_t)2 * BK * (LDA + LDB) * sizeof(float))

__global__ __launch_bounds__(256, 1)
void sgemm_nt_part(const float* __restrict__ A,
                   const float* __restrict__ Bm,
                   float* __restrict__ Part,
                   int M, int N, int K, int Kc)
{
    extern __shared__ float sm[];
    float (*As)[BK][LDA] = (float (*)[BK][LDA])sm;
    float (*Bs)[BK][LDB] = (float (*)[BK][LDB])(sm + 2 * BK * LDA);

    const int tid  = threadIdx.x;
    const int bm   = blockIdx.y * BM;
    const int bn   = blockIdx.x * BN;
    const int s    = blockIdx.z;
    const int kb   = s * Kc;

    const int warp = tid >> 5;
    const int lane = tid & 31;
    // warp grid: 2 warps along M (128 rows each), 4 warps along N (32 cols)
    const int m0 = (warp & 1) * 128 + (lane >> 2) * 16;
    const int n0 = (warp >> 1) * 32 + (lane & 3) * 8;

    // global->smem loader mapping
    const int lr = tid >> 2;          // base row 0..63
    const int c4 = (tid & 3) * 4;     // k-offset 0,4,8,12

    const float* Ap = A  + (size_t)bm * K + kb;
    const float* Bp = Bm + (size_t)bn * K + kb;

    float acc[16][8];
#pragma unroll
    for (int i = 0; i < 16; i++)
#pragma unroll
        for (int j = 0; j < 8; j++) acc[i][j] = 0.0f;

    const int NT = Kc / BK;
    float4 ar[4], br[2];
    float af[2][16], bf[2][8];

    // ---- prologue: global tile 0 -> smem buffer 0 ----
#pragma unroll
    for (int i = 0; i < 4; i++)
        ar[i] = *(const float4*)(Ap + (size_t)(lr + i * 64) * K + c4);
#pragma unroll
    for (int i = 0; i < 2; i++)
        br[i] = *(const float4*)(Bp + (size_t)(lr + i * 64) * K + c4);
#pragma unroll
    for (int i = 0; i < 4; i++) {
        const int r = lr + i * 64;
        As[0][c4 + 0][r] = ar[i].x; As[0][c4 + 1][r] = ar[i].y;
        As[0][c4 + 2][r] = ar[i].z; As[0][c4 + 3][r] = ar[i].w;
    }
#pragma unroll
    for (int i = 0; i < 2; i++) {
        const int r = lr + i * 64;
        Bs[0][c4 + 0][r] = br[i].x; Bs[0][c4 + 1][r] = br[i].y;
        Bs[0][c4 + 2][r] = br[i].z; Bs[0][c4 + 3][r] = br[i].w;
    }
    __syncthreads();

    for (int kt = 0; kt < NT; kt++) {
        const int cur = kt & 1;

        // prefetch next global tile into registers (LDG hidden under compute)
        if (kt + 1 < NT) {
            const int k0 = (kt + 1) * BK;
#pragma unroll
            for (int i = 0; i < 4; i++)
                ar[i] = *(const float4*)(Ap + (size_t)(lr + i * 64) * K + k0 + c4);
#pragma unroll
            for (int i = 0; i < 2; i++)
                br[i] = *(const float4*)(Bp + (size_t)(lr + i * 64) * K + k0 + c4);
        }

        // preload fragments for k=0
#pragma unroll
        for (int i = 0; i < 4; i++)
            *(float4*)(af[0] + i * 4) = *(const float4*)&As[cur][0][m0 + i * 4];
        *(float4*)(bf[0])     = *(const float4*)&Bs[cur][0][n0];
        *(float4*)(bf[0] + 4) = *(const float4*)&Bs[cur][0][n0 + 4];

        // compute: ascending k; frag prefetch for k+1 issued before k's FFMAs
#pragma unroll
        for (int k = 0; k < BK; k++) {
            const int pb = k & 1;
            if (k + 1 < BK) {
                const int nb = pb ^ 1;
#pragma unroll
                for (int i = 0; i < 4; i++)
                    *(float4*)(af[nb] + i * 4) =
                        *(const float4*)&As[cur][k + 1][m0 + i * 4];
                *(float4*)(bf[nb])     = *(const float4*)&Bs[cur][k + 1][n0];
                *(float4*)(bf[nb] + 4) = *(const float4*)&Bs[cur][k + 1][n0 + 4];
            }
#pragma unroll
            for (int i = 0; i < 16; i++)
#pragma unroll
                for (int j = 0; j < 8; j++)
                    acc[i][j] = __fmaf_rn(af[pb][i], bf[pb][j], acc[i][j]);
        }

        if (kt + 1 < NT) {
            const int nxt = cur ^ 1;
#pragma unroll
            for (int i = 0; i < 4; i++) {
                const int r = lr + i * 64;
                As[nxt][c4 + 0][r] = ar[i].x; As[nxt][c4 + 1][r] = ar[i].y;
                As[nxt][c4 + 2][r] = ar[i].z; As[nxt][c4 + 3][r] = ar[i].w;
            }
#pragma unroll
            for (int i = 0; i < 2; i++) {
                const int r = lr + i * 64;
                Bs[nxt][c4 + 0][r] = br[i].x; Bs[nxt][c4 + 1][r] = br[i].y;
                Bs[nxt][c4 + 2][r] = br[i].z; Bs[nxt][c4 + 3][r] = br[i].w;
            }
            __syncthreads();
        }
    }

    // epilogue: raw partials (no bias here — reduce+bias fused into LIF)
    float* base = Part + (size_t)s * M * N + (size_t)(bm + m0) * N + bn + n0;
#pragma unroll
    for (int i = 0; i < 16; i++) {
        *(float4*)(base + (size_t)i * N)     =
            make_float4(acc[i][0], acc[i][1], acc[i][2], acc[i][3]);
        *(float4*)(base + (size_t)i * N + 4) =
            make_float4(acc[i][4], acc[i][5], acc[i][6], acc[i][7]);
    }
}

// ---------------------------------------------------------------------------
// LIF scans with fused split-K reduce + bias.
// Reduce: t = p0; t = t + p1; ... (ascending s, each add rounded); c = t + bias.
// LIF: u = 0.95*mem; u = u + c; mem = u - rst  (separately rounded ops).
// Identical rounding sequence to the passing version.
// ---------------------------------------------------------------------------
__global__ void lif_scan1(const float* __restrict__ part,
                          const float* __restrict__ bias,
                          float* __restrict__ spk1)
{
    const int idx = blockIdx.x * blockDim.x + threadIdx.x;
    if (idx >= BB * NHID) return;
    const size_t stride  = (size_t)BB * NHID;
    const size_t pstride = (size_t)TT * BB * NHID;  // split stride
    const float  bv = bias[idx % NHID];
    size_t off = idx;
    float mem = 0.0f;
#pragma unroll 4
    for (int t = 0; t < TT; t++) {
        float c = __fadd_rn(part[off], part[pstride + off]);
        c = __fadd_rn(c, bv);
        const float rst = (mem > THRESH) ? THRESH : 0.0f;
        float u = __fmul_rn(BETA, mem);
        u = __fadd_rn(u, c);
        mem = __fsub_rn(u, rst);
        spk1[off] = (mem > THRESH) ? 1.0f : 0.0f;
        off += stride;
    }
}

__global__ void lif_scan2(const float* __restrict__ part,
                          const float* __restrict__ bias,
                          float* __restrict__ out)
{
    const int idx = blockIdx.x * blockDim.x + threadIdx.x;
    if (idx >= BB * NOUT) return;
    const size_t stride  = (size_t)BB * NOUT;
    const size_t pstride = (size_t)TT * BB * NOUT;
    const size_t half    = (size_t)TT * BB * NOUT;
    const float  bv = bias[idx % NOUT];
    size_t off = idx;
    float mem = 0.0f;
    for (int t = 0; t < TT; t++) {
        float c = part[off];
#pragma unroll
        for (int s = 1; s < SPLIT2; s++)
            c = __fadd_rn(c, part[(size_t)s * pstride + off]);
        c = __fadd_rn(c, bv);
        const float rst = (mem > THRESH) ? THRESH : 0.0f;
        float u = __fmul_rn(BETA, mem);
        u = __fadd_rn(u, c);
        mem = __fsub_rn(u, rst);
        out[off]        = (mem > THRESH) ? 1.0f : 0.0f;  // spk_rec
        out[half + off] = mem;                           // mem_rec
        off += stride;
    }
}

// ---------------------------------------------------------------------------
// Launch
// ---------------------------------------------------------------------------
extern "C" void kernel_launch(void* const* d_in, const int* in_sizes, int n_in,
                              void* d_out, int out_size)
{
    const float* x  = (const float*)d_in[0];   // [T,B,NIN]
    const float* W1 = (const float*)d_in[1];   // [NHID,NIN]
    const float* b1 = (const float*)d_in[2];   // [NHID]
    const float* W2 = (const float*)d_in[3];   // [NOUT,NHID]
    const float* b2 = (const float*)d_in[4];   // [NOUT]
    float* out = (float*)d_out;

    float* spk1; cudaGetSymbolAddress((void**)&spk1, g_spk1);
    float* part; cudaGetSymbolAddress((void**)&part, g_part);

    // opt-in smem (idempotent host-side attribute set; capture-safe)
    cudaFuncSetAttribute(sgemm_nt_part,
                         cudaFuncAttributeMaxDynamicSharedMemorySize,
                         (int)GEMM_SMEM);

    const int M = TT * BB;  // 25600

    // GEMM1 partials: split-K = 2 over K=1024 (chunks of 512)
    {
        dim3 grid(NHID / BN, M / BM, SPLIT1);
        sgemm_nt_part<<<grid, 256, GEMM_SMEM>>>(x, W1, part, M, NHID, NIN, NIN / SPLIT1);
    }

    // LIF scan layer 1 (fused split-K reduce + bias) -> spike train
    {
        const int n = BB * NHID;
        lif_scan1<<<(n + 255) / 256, 256>>>(part, b1, spk1);
    }

    // GEMM2 partials: split-K = 16 over K=4096 (chunks of 256)
    {
        dim3 grid(NOUT / BN, M / BM, SPLIT2);
        sgemm_nt_part<<<grid, 256, GEMM_SMEM>>>(spk1, W2, part, M, NOUT, NHID, NHID / SPLIT2);
    }

    // LIF scan layer 2 (fused reduce + bias) -> d_out (spk_rec || mem_rec)
    {
        const int n = BB * NOUT;
        lif_scan2<<<(n + 255) / 256, 256>>>(part, b2, out);
    }
}

// round 10
// speedup vs baseline: 1.0385x; 1.0385x over previous
#include <cuda_runtime.h>
#include <cstdint>

// Problem constants
#define TT   100
#define BB   256
#define NIN  1024
#define NHID 4096
#define NOUT 512

#define BETA   0.95f
#define THRESH 1.0f

// Confirmed reference arithmetic: cuBLASLt serial split-K.
// GEMM1 (per-step 256x4096x1024): S=2.  GEMM2 (256x512x4096): S=16.
#define SPLIT1 2
#define SPLIT2 16

// Scratch (allocation-free rule: __device__ globals)
__device__ float g_spk1[(size_t)TT * BB * NHID];        // 419 MB
// Partial buffer: 2*M*NHID == 16*M*NOUT == 209,715,200 floats (839 MB)
__device__ float g_part[(size_t)16 * TT * BB * NOUT];

// ---------------------------------------------------------------------------
// Packed fp32 FMA: two independent IEEE fp32 RN FMAs per instruction.
// Lane-wise: low 32 bits and high 32 bits are separate fp32 lanes, each
// computing fmaf_rn — bitwise identical per lane to scalar FFMA chains.
// ---------------------------------------------------------------------------
__device__ __forceinline__ void fma_f32x2(unsigned long long& acc,
                                          unsigned long long a2,
                                          unsigned long long b2) {
    asm("fma.rn.f32x2 %0, %1, %2, %0;" : "+l"(acc) : "l"(a2), "l"(b2));
}
__device__ __forceinline__ unsigned long long pack_dup(float x) {
    unsigned long long r;
    asm("mov.b64 %0, {%1, %1};" : "=l"(r) : "f"(x));
    return r;
}
__device__ __forceinline__ unsigned long long pack2(float lo, float hi) {
    unsigned long long r;
    asm("mov.b64 %0, {%1, %2};" : "=l"(r) : "f"(lo), "f"(hi));
    return r;
}
__device__ __forceinline__ void unpack2(unsigned long long v, float& lo, float& hi) {
    asm("mov.b64 {%0, %1}, %2;" : "=f"(lo), "=f"(hi) : "l"(v));
}

// ---------------------------------------------------------------------------
// Partial SGEMM (NT): Part[s][M][N] = A[M, ks..ks+Kc) @ B[N, ks..ks+Kc)^T
// BM=256 x BN=128 tile, BK=16, 256 threads, 16x8 micro-tile per thread.
// Round-8 structure (double-buffered smem tiles, register-staged LDG,
// single-buffered fragments) + FFMA2 packed compute.
// NUMERICS: per output element a single fp32 accumulator lane folded by an
// ascending-k FMA chain from 0 — bitwise identical to the passing kernel.
// ---------------------------------------------------------------------------
#define BM 256
#define BN 128
#define BK 16
#define LDA (BM + 4)
#define LDB (BN + 4)
#define GEMM_SMEM ((size_t)2 * BK * (LDA + LDB) * sizeof(float))

__global__ __launch_bounds__(256, 1)
void sgemm_nt_part(const float* __restrict__ A,
                   const float* __restrict__ Bm,
                   float* __restrict__ Part,
                   int M, int N, int K, int Kc)
{
    extern __shared__ float sm[];
    float (*As)[BK][LDA] = (float (*)[BK][LDA])sm;
    float (*Bs)[BK][LDB] = (float (*)[BK][LDB])(sm + 2 * BK * LDA);

    const int tid  = threadIdx.x;
    const int bm   = blockIdx.y * BM;
    const int bn   = blockIdx.x * BN;
    const int s    = blockIdx.z;
    const int kb   = s * Kc;

    const int warp = tid >> 5;
    const int lane = tid & 31;
    // warp grid: 2 warps along M (128 rows each), 4 warps along N (32 cols)
    const int m0 = (warp & 1) * 128 + (lane >> 2) * 16;
    const int n0 = (warp >> 1) * 32 + (lane & 3) * 8;

    // global->smem loader mapping
    const int lr = tid >> 2;          // base row 0..63
    const int c4 = (tid & 3) * 4;     // k-offset 0,4,8,12

    const float* Ap = A  + (size_t)bm * K + kb;
    const float* Bp = Bm + (size_t)bn * K + kb;

    // Packed accumulators: accp[i][j] holds output cols (2j, 2j+1) for row i.
    unsigned long long accp[16][4];
#pragma unroll
    for (int i = 0; i < 16; i++)
#pragma unroll
        for (int j = 0; j < 4; j++) accp[i][j] = 0ull;

    const int NT = Kc / BK;
    float4 ar[4], br[2];

    // ---- prologue: global tile 0 -> smem buffer 0 ----
#pragma unroll
    for (int i = 0; i < 4; i++)
        ar[i] = *(const float4*)(Ap + (size_t)(lr + i * 64) * K + c4);
#pragma unroll
    for (int i = 0; i < 2; i++)
        br[i] = *(const float4*)(Bp + (size_t)(lr + i * 64) * K + c4);
#pragma unroll
    for (int i = 0; i < 4; i++) {
        const int r = lr + i * 64;
        As[0][c4 + 0][r] = ar[i].x; As[0][c4 + 1][r] = ar[i].y;
        As[0][c4 + 2][r] = ar[i].z; As[0][c4 + 3][r] = ar[i].w;
    }
#pragma unroll
    for (int i = 0; i < 2; i++) {
        const int r = lr + i * 64;
        Bs[0][c4 + 0][r] = br[i].x; Bs[0][c4 + 1][r] = br[i].y;
        Bs[0][c4 + 2][r] = br[i].z; Bs[0][c4 + 3][r] = br[i].w;
    }
    __syncthreads();

    for (int kt = 0; kt < NT; kt++) {
        const int cur = kt & 1;

        // prefetch next global tile into registers (LDG hidden under compute)
        if (kt + 1 < NT) {
            const int k0 = (kt + 1) * BK;
#pragma unroll
            for (int i = 0; i < 4; i++)
                ar[i] = *(const float4*)(Ap + (size_t)(lr + i * 64) * K + k0 + c4);
#pragma unroll
            for (int i = 0; i < 2; i++)
                br[i] = *(const float4*)(Bp + (size_t)(lr + i * 64) * K + k0 + c4);
        }

        // compute: ascending k within the tile (per-lane chain order preserved)
#pragma unroll
        for (int k = 0; k < BK; k++) {
            float a[16], b[8];
#pragma unroll
            for (int i = 0; i < 4; i++)
                *(float4*)(a + i * 4) = *(const float4*)&As[cur][k][m0 + i * 4];
            *(float4*)(b)     = *(const float4*)&Bs[cur][k][n0];
            *(float4*)(b + 4) = *(const float4*)&Bs[cur][k][n0 + 4];

            unsigned long long bp[4];
#pragma unroll
            for (int j = 0; j < 4; j++)
                bp[j] = pack2(b[2 * j], b[2 * j + 1]);
#pragma unroll
            for (int i = 0; i < 16; i++) {
                const unsigned long long apd = pack_dup(a[i]);
#pragma unroll
                for (int j = 0; j < 4; j++)
                    fma_f32x2(accp[i][j], apd, bp[j]);
            }
        }

        if (kt + 1 < NT) {
            const int nxt = cur ^ 1;
#pragma unroll
            for (int i = 0; i < 4; i++) {
                const int r = lr + i * 64;
                As[nxt][c4 + 0][r] = ar[i].x; As[nxt][c4 + 1][r] = ar[i].y;
                As[nxt][c4 + 2][r] = ar[i].z; As[nxt][c4 + 3][r] = ar[i].w;
            }
#pragma unroll
            for (int i = 0; i < 2; i++) {
                const int r = lr + i * 64;
                Bs[nxt][c4 + 0][r] = br[i].x; Bs[nxt][c4 + 1][r] = br[i].y;
                Bs[nxt][c4 + 2][r] = br[i].z; Bs[nxt][c4 + 3][r] = br[i].w;
            }
            __syncthreads();
        }
    }

    // epilogue: unpack and store raw partials (reduce+bias fused into LIF)
    float* base = Part + (size_t)s * M * N + (size_t)(bm + m0) * N + bn + n0;
#pragma unroll
    for (int i = 0; i < 16; i++) {
        float o[8];
#pragma unroll
        for (int j = 0; j < 4; j++)
            unpack2(accp[i][j], o[2 * j], o[2 * j + 1]);
        *(float4*)(base + (size_t)i * N)     = make_float4(o[0], o[1], o[2], o[3]);
        *(float4*)(base + (size_t)i * N + 4) = make_float4(o[4], o[5], o[6], o[7]);
    }
}

// ---------------------------------------------------------------------------
// LIF scans with fused split-K reduce + bias.
// Reduce: t = p0; t = t + p1; ... (ascending s, each add rounded); c = t + bias.
// LIF: u = 0.95*mem; u = u + c; mem = u - rst  (separately rounded ops).
// Identical rounding sequence to the passing version.
// ---------------------------------------------------------------------------
__global__ void lif_scan1(const float* __restrict__ part,
                          const float* __restrict__ bias,
                          float* __restrict__ spk1)
{
    const int idx = blockIdx.x * blockDim.x + threadIdx.x;
    if (idx >= BB * NHID) return;
    const size_t stride  = (size_t)BB * NHID;
    const size_t pstride = (size_t)TT * BB * NHID;  // split stride
    const float  bv = bias[idx % NHID];
    size_t off = idx;
    float mem = 0.0f;
#pragma unroll 4
    for (int t = 0; t < TT; t++) {
        float c = __fadd_rn(part[off], part[pstride + off]);
        c = __fadd_rn(c, bv);
        const float rst = (mem > THRESH) ? THRESH : 0.0f;
        float u = __fmul_rn(BETA, mem);
        u = __fadd_rn(u, c);
        mem = __fsub_rn(u, rst);
        spk1[off] = (mem > THRESH) ? 1.0f : 0.0f;
        off += stride;
    }
}

__global__ void lif_scan2(const float* __restrict__ part,
                          const float* __restrict__ bias,
                          float* __restrict__ out)
{
    const int idx = blockIdx.x * blockDim.x + threadIdx.x;
    if (idx >= BB * NOUT) return;
    const size_t stride  = (size_t)BB * NOUT;
    const size_t pstride = (size_t)TT * BB * NOUT;
    const size_t half    = (size_t)TT * BB * NOUT;
    const float  bv = bias[idx % NOUT];
    size_t off = idx;
    float mem = 0.0f;
    for (int t = 0; t < TT; t++) {
        float c = part[off];
#pragma unroll
        for (int s = 1; s < SPLIT2; s++)
            c = __fadd_rn(c, part[(size_t)s * pstride + off]);
        c = __fadd_rn(c, bv);
        const float rst = (mem > THRESH) ? THRESH : 0.0f;
        float u = __fmul_rn(BETA, mem);
        u = __fadd_rn(u, c);
        mem = __fsub_rn(u, rst);
        out[off]        = (mem > THRESH) ? 1.0f : 0.0f;  // spk_rec
        out[half + off] = mem;                           // mem_rec
        off += stride;
    }
}

// ---------------------------------------------------------------------------
// Launch
// ---------------------------------------------------------------------------
extern "C" void kernel_launch(void* const* d_in, const int* in_sizes, int n_in,
                              void* d_out, int out_size)
{
    const float* x  = (const float*)d_in[0];   // [T,B,NIN]
    const float* W1 = (const float*)d_in[1];   // [NHID,NIN]
    const float* b1 = (const float*)d_in[2];   // [NHID]
    const float* W2 = (const float*)d_in[3];   // [NOUT,NHID]
    const float* b2 = (const float*)d_in[4];   // [NOUT]
    float* out = (float*)d_out;

    float* spk1; cudaGetSymbolAddress((void**)&spk1, g_spk1);
    float* part; cudaGetSymbolAddress((void**)&part, g_part);

    // opt-in smem (idempotent host-side attribute set; capture-safe)
    cudaFuncSetAttribute(sgemm_nt_part,
                         cudaFuncAttributeMaxDynamicSharedMemorySize,
                         (int)GEMM_SMEM);

    const int M = TT * BB;  // 25600

    // GEMM1 partials: split-K = 2 over K=1024 (chunks of 512)
    {
        dim3 grid(NHID / BN, M / BM, SPLIT1);
        sgemm_nt_part<<<grid, 256, GEMM_SMEM>>>(x, W1, part, M, NHID, NIN, NIN / SPLIT1);
    }

    // LIF scan layer 1 (fused split-K reduce + bias) -> spike train
    {
        const int n = BB * NHID;
        lif_scan1<<<(n + 255) / 256, 256>>>(part, b1, spk1);
    }

    // GEMM2 partials: split-K = 16 over K=4096 (chunks of 256)
    {
        dim3 grid(NOUT / BN, M / BM, SPLIT2);
        sgemm_nt_part<<<grid, 256, GEMM_SMEM>>>(spk1, W2, part, M, NOUT, NHID, NHID / SPLIT2);
    }

    // LIF scan layer 2 (fused reduce + bias) -> d_out (spk_rec || mem_rec)
    {
        const int n = BB * NOUT;
        lif_scan2<<<(n + 255) / 256, 256>>>(part, b2, out);
    }
}

// round 11
// speedup vs baseline: 1.0488x; 1.0099x over previous
#include <cuda_runtime.h>
#include <cstdint>

// Problem constants
#define TT   100
#define BB   256
#define NIN  1024
#define NHID 4096
#define NOUT 512

#define BETA   0.95f
#define THRESH 1.0f

// Confirmed reference arithmetic: cuBLASLt serial split-K.
#define SPLIT1 2
#define SPLIT2 16

// Scratch (allocation-free rule: __device__ globals)
__device__ float g_spk1[(size_t)TT * BB * NHID];        // 419 MB
__device__ float g_part[(size_t)16 * TT * BB * NOUT];   // 839 MB

// ---------------------------------------------------------------------------
// Packed fp32 FMA: two independent IEEE fp32 RN FMAs per instruction.
// ---------------------------------------------------------------------------
__device__ __forceinline__ void fma_f32x2(unsigned long long& acc,
                                          unsigned long long a2,
                                          unsigned long long b2) {
    asm("fma.rn.f32x2 %0, %1, %2, %0;" : "+l"(acc) : "l"(a2), "l"(b2));
}
__device__ __forceinline__ unsigned long long pack_dup(float x) {
    unsigned long long r;
    asm("mov.b64 %0, {%1, %1};" : "=l"(r) : "f"(x));
    return r;
}
__device__ __forceinline__ unsigned long long pack2(float lo, float hi) {
    unsigned long long r;
    asm("mov.b64 %0, {%1, %2};" : "=l"(r) : "f"(lo), "f"(hi));
    return r;
}
__device__ __forceinline__ void unpack2(unsigned long long v, float& lo, float& hi) {
    asm("mov.b64 {%0, %1}, %2;" : "=f"(lo), "=f"(hi) : "l"(v));
}

// ---------------------------------------------------------------------------
// Partial SGEMM (NT): Part[s][M][N] = A[M, ks..ks+Kc) @ B[N, ks..ks+Kc)^T
// BM=256 x BN=128 tile, BK=16, 256 threads, 16x8 micro-tile per thread.
// A smem layout: per-16-row 4-word pad so the 8 per-warp fragment LDS.128
// groups partition all 32 banks (removes the 4-way A-frag conflict):
//   word(k, m) = k*LDA + m + ((m>>4)<<2),  LDA = 324.
// NUMERICS: per output element, one fp32 accumulator lane folded by an
// ascending-k FMA chain from 0 — bitwise identical to the passing kernel.
// ---------------------------------------------------------------------------
#define BM 256
#define BN 128
#define BK 16
#define LDA 324                       // 256 + 16 group pads of 4 + 4 tail
#define LDB (BN + 4)
#define ABUF ((size_t)BK * LDA)
#define BBUF ((size_t)BK * LDB)
#define GEMM_SMEM ((size_t)2 * (ABUF + BBUF) * sizeof(float))

#define AIDX(k, m) ((k) * LDA + (m) + (((m) >> 4) << 2))

__global__ __launch_bounds__(256, 1)
void sgemm_nt_part(const float* __restrict__ A,
                   const float* __restrict__ Bm,
                   float* __restrict__ Part,
                   int M, int N, int K, int Kc)
{
    extern __shared__ float sm[];
    float* Abase = sm;                       // 2 buffers of BK*LDA
    float (*Bs)[BK][LDB] = (float (*)[BK][LDB])(sm + 2 * ABUF);

    const int tid  = threadIdx.x;
    const int bm   = blockIdx.y * BM;
    const int bn   = blockIdx.x * BN;
    const int s    = blockIdx.z;
    const int kb   = s * Kc;

    const int warp = tid >> 5;
    const int lane = tid & 31;
    // warp grid: 2 warps along M (128 rows each), 4 warps along N (32 cols)
    const int m0 = (warp & 1) * 128 + (lane >> 2) * 16;
    const int n0 = (warp >> 1) * 32 + (lane & 3) * 8;
    const int mpad = m0 + ((m0 >> 4) << 2);  // padded base for frag loads

    // global->smem loader mapping
    const int lr = tid >> 2;          // base row 0..63
    const int c4 = (tid & 3) * 4;     // k-offset 0,4,8,12

    const float* Ap = A  + (size_t)bm * K + kb;
    const float* Bp = Bm + (size_t)bn * K + kb;

    // Packed accumulators: accp[i][j] = output cols (2j, 2j+1) for row i.
    unsigned long long accp[16][4];
#pragma unroll
    for (int i = 0; i < 16; i++)
#pragma unroll
        for (int j = 0; j < 4; j++) accp[i][j] = 0ull;

    const int NT = Kc / BK;
    float4 ar[4], br[2];

    // ---- prologue: global tile 0 -> smem buffer 0 ----
#pragma unroll
    for (int i = 0; i < 4; i++)
        ar[i] = *(const float4*)(Ap + (size_t)(lr + i * 64) * K + c4);
#pragma unroll
    for (int i = 0; i < 2; i++)
        br[i] = *(const float4*)(Bp + (size_t)(lr + i * 64) * K + c4);
#pragma unroll
    for (int i = 0; i < 4; i++) {
        const int r = lr + i * 64;
        Abase[AIDX(c4 + 0, r)] = ar[i].x; Abase[AIDX(c4 + 1, r)] = ar[i].y;
        Abase[AIDX(c4 + 2, r)] = ar[i].z; Abase[AIDX(c4 + 3, r)] = ar[i].w;
    }
#pragma unroll
    for (int i = 0; i < 2; i++) {
        const int r = lr + i * 64;
        Bs[0][c4 + 0][r] = br[i].x; Bs[0][c4 + 1][r] = br[i].y;
        Bs[0][c4 + 2][r] = br[i].z; Bs[0][c4 + 3][r] = br[i].w;
    }
    __syncthreads();

    for (int kt = 0; kt < NT; kt++) {
        const int cur = kt & 1;
        const float* Ab = Abase + cur * ABUF;

        // prefetch next global tile into registers (LDG hidden under compute)
        if (kt + 1 < NT) {
            const int k0 = (kt + 1) * BK;
#pragma unroll
            for (int i = 0; i < 4; i++)
                ar[i] = *(const float4*)(Ap + (size_t)(lr + i * 64) * K + k0 + c4);
#pragma unroll
            for (int i = 0; i < 2; i++)
                br[i] = *(const float4*)(Bp + (size_t)(lr + i * 64) * K + k0 + c4);
        }

        // compute: ascending k within the tile (per-lane chain order preserved)
#pragma unroll
        for (int k = 0; k < BK; k++) {
            float a[16], b[8];
#pragma unroll
            for (int i = 0; i < 4; i++)
                *(float4*)(a + i * 4) =
                    *(const float4*)&Ab[k * LDA + mpad + 4 * i];
            *(float4*)(b)     = *(const float4*)&Bs[cur][k][n0];
            *(float4*)(b + 4) = *(const float4*)&Bs[cur][k][n0 + 4];

            unsigned long long bp[4];
#pragma unroll
            for (int j = 0; j < 4; j++)
                bp[j] = pack2(b[2 * j], b[2 * j + 1]);
#pragma unroll
            for (int i = 0; i < 16; i++) {
                const unsigned long long apd = pack_dup(a[i]);
#pragma unroll
                for (int j = 0; j < 4; j++)
                    fma_f32x2(accp[i][j], apd, bp[j]);
            }
        }

        if (kt + 1 < NT) {
            float* An = Abase + (cur ^ 1) * ABUF;
#pragma unroll
            for (int i = 0; i < 4; i++) {
                const int r = lr + i * 64;
                An[AIDX(c4 + 0, r)] = ar[i].x; An[AIDX(c4 + 1, r)] = ar[i].y;
                An[AIDX(c4 + 2, r)] = ar[i].z; An[AIDX(c4 + 3, r)] = ar[i].w;
            }
            const int nxt = cur ^ 1;
#pragma unroll
            for (int i = 0; i < 2; i++) {
                const int r = lr + i * 64;
                Bs[nxt][c4 + 0][r] = br[i].x; Bs[nxt][c4 + 1][r] = br[i].y;
                Bs[nxt][c4 + 2][r] = br[i].z; Bs[nxt][c4 + 3][r] = br[i].w;
            }
            __syncthreads();
        }
    }

    // epilogue: unpack and store raw partials (reduce+bias fused into LIF)
    float* base = Part + (size_t)s * M * N + (size_t)(bm + m0) * N + bn + n0;
#pragma unroll
    for (int i = 0; i < 16; i++) {
        float o[8];
#pragma unroll
        for (int j = 0; j < 4; j++)
            unpack2(accp[i][j], o[2 * j], o[2 * j + 1]);
        *(float4*)(base + (size_t)i * N)     = make_float4(o[0], o[1], o[2], o[3]);
        *(float4*)(base + (size_t)i * N + 4) = make_float4(o[4], o[5], o[6], o[7]);
    }
}

// ---------------------------------------------------------------------------
// LIF scans with fused split-K reduce + bias (rounding sequence unchanged).
// ---------------------------------------------------------------------------
__global__ void lif_scan1(const float* __restrict__ part,
                          const float* __restrict__ bias,
                          float* __restrict__ spk1)
{
    const int idx = blockIdx.x * blockDim.x + threadIdx.x;
    if (idx >= BB * NHID) return;
    const size_t stride  = (size_t)BB * NHID;
    const size_t pstride = (size_t)TT * BB * NHID;
    const float  bv = bias[idx % NHID];
    size_t off = idx;
    float mem = 0.0f;
#pragma unroll 4
    for (int t = 0; t < TT; t++) {
        float c = __fadd_rn(part[off], part[pstride + off]);
        c = __fadd_rn(c, bv);
        const float rst = (mem > THRESH) ? THRESH : 0.0f;
        float u = __fmul_rn(BETA, mem);
        u = __fadd_rn(u, c);
        mem = __fsub_rn(u, rst);
        spk1[off] = (mem > THRESH) ? 1.0f : 0.0f;
        off += stride;
    }
}

__global__ void lif_scan2(const float* __restrict__ part,
                          const float* __restrict__ bias,
                          float* __restrict__ out)
{
    const int idx = blockIdx.x * blockDim.x + threadIdx.x;
    if (idx >= BB * NOUT) return;
    const size_t stride  = (size_t)BB * NOUT;
    const size_t pstride = (size_t)TT * BB * NOUT;
    const size_t half    = (size_t)TT * BB * NOUT;
    const float  bv = bias[idx % NOUT];
    size_t off = idx;
    float mem = 0.0f;
    for (int t = 0; t < TT; t++) {
        float c = part[off];
#pragma unroll
        for (int s = 1; s < SPLIT2; s++)
            c = __fadd_rn(c, part[(size_t)s * pstride + off]);
        c = __fadd_rn(c, bv);
        const float rst = (mem > THRESH) ? THRESH : 0.0f;
        float u = __fmul_rn(BETA, mem);
        u = __fadd_rn(u, c);
        mem = __fsub_rn(u, rst);
        out[off]        = (mem > THRESH) ? 1.0f : 0.0f;  // spk_rec
        out[half + off] = mem;                           // mem_rec
        off += stride;
    }
}

// ---------------------------------------------------------------------------
// Launch
// ---------------------------------------------------------------------------
extern "C" void kernel_launch(void* const* d_in, const int* in_sizes, int n_in,
                              void* d_out, int out_size)
{
    const float* x  = (const float*)d_in[0];   // [T,B,NIN]
    const float* W1 = (const float*)d_in[1];   // [NHID,NIN]
    const float* b1 = (const float*)d_in[2];   // [NHID]
    const float* W2 = (const float*)d_in[3];   // [NOUT,NHID]
    const float* b2 = (const float*)d_in[4];   // [NOUT]
    float* out = (float*)d_out;

    float* spk1; cudaGetSymbolAddress((void**)&spk1, g_spk1);
    float* part; cudaGetSymbolAddress((void**)&part, g_part);

    cudaFuncSetAttribute(sgemm_nt_part,
                         cudaFuncAttributeMaxDynamicSharedMemorySize,
                         (int)GEMM_SMEM);

    const int M = TT * BB;  // 25600

    // GEMM1 partials: split-K = 2 over K=1024
    {
        dim3 grid(NHID / BN, M / BM, SPLIT1);
        sgemm_nt_part<<<grid, 256, GEMM_SMEM>>>(x, W1, part, M, NHID, NIN, NIN / SPLIT1);
    }

    // LIF scan layer 1 (fused split-K reduce + bias) -> spike train
    {
        const int n = BB * NHID;
        lif_scan1<<<(n + 255) / 256, 256>>>(part, b1, spk1);
    }

    // GEMM2 partials: split-K = 16 over K=4096
    {
        dim3 grid(NOUT / BN, M / BM, SPLIT2);
        sgemm_nt_part<<<grid, 256, GEMM_SMEM>>>(spk1, W2, part, M, NOUT, NHID, NHID / SPLIT2);
    }

    // LIF scan layer 2 (fused reduce + bias) -> d_out (spk_rec || mem_rec)
    {
        const int n = BB * NOUT;
        lif_scan2<<<(n + 255) / 256, 256>>>(part, b2, out);
    }
}

// round 12
// speedup vs baseline: 1.1902x; 1.1349x over previous
#include <cuda_runtime.h>
#include <cstdint>

// Problem constants
#define TT   100
#define BB   256
#define NIN  1024
#define NHID 4096
#define NOUT 512

#define BETA   0.95f
#define THRESH 1.0f

// Confirmed reference arithmetic: cuBLASLt serial split-K.
#define SPLIT1 2
#define SPLIT2 16

// Scratch (allocation-free rule: __device__ globals)
__device__ float g_spk1[(size_t)TT * BB * NHID];        // 419 MB
__device__ float g_part[(size_t)16 * TT * BB * NOUT];   // 839 MB

// ---------------------------------------------------------------------------
// Packed fp32 FMA: two independent IEEE fp32 RN FMAs per instruction.
// ---------------------------------------------------------------------------
__device__ __forceinline__ void fma_f32x2(unsigned long long& acc,
                                          unsigned long long a2,
                                          unsigned long long b2) {
    asm("fma.rn.f32x2 %0, %1, %2, %0;" : "+l"(acc) : "l"(a2), "l"(b2));
}
__device__ __forceinline__ unsigned long long pack_dup(float x) {
    unsigned long long r;
    asm("mov.b64 %0, {%1, %1};" : "=l"(r) : "f"(x));
    return r;
}
__device__ __forceinline__ void unpack2(unsigned long long v, float& lo, float& hi) {
    asm("mov.b64 {%0, %1}, %2;" : "=f"(lo), "=f"(hi) : "l"(v));
}

// ---------------------------------------------------------------------------
// Partial SGEMM (NT): Part[s][M][N] = A[M, ks..ks+Kc) @ B[N, ks..ks+Kc)^T
// BM=256 x BN=128 tile, BK=16, 256 threads, 16x8 micro-tile per thread.
// FFMA2 pairs ROWS: the A lane-pair comes directly from the LDS.128 register
// quad (no MOVs); only B is duplicated (8 pack_dup per k, was 16 dup + 4 pack).
// A smem: per-16-row 4-word pad -> conflict-free frag loads (LDA=324).
// NUMERICS: per output element, one fp32 accumulator lane folded by an
// ascending-k FMA chain from 0 — bitwise identical to the passing kernel.
// ---------------------------------------------------------------------------
#define BM 256
#define BN 128
#define BK 16
#define LDA 324
#define LDB (BN + 4)
#define ABUF ((size_t)BK * LDA)
#define BBUF ((size_t)BK * LDB)
#define GEMM_SMEM ((size_t)2 * (ABUF + BBUF) * sizeof(float))

#define AIDX(k, m) ((k) * LDA + (m) + (((m) >> 4) << 2))

__global__ __launch_bounds__(256, 1)
void sgemm_nt_part(const float* __restrict__ A,
                   const float* __restrict__ Bm,
                   float* __restrict__ Part,
                   int M, int N, int K, int Kc)
{
    extern __shared__ float sm[];
    float* Abase = sm;                       // 2 buffers of BK*LDA
    float (*Bs)[BK][LDB] = (float (*)[BK][LDB])(sm + 2 * ABUF);

    const int tid  = threadIdx.x;
    const int bm   = blockIdx.y * BM;
    const int bn   = blockIdx.x * BN;
    const int s    = blockIdx.z;
    const int kb   = s * Kc;

    const int warp = tid >> 5;
    const int lane = tid & 31;
    const int m0 = (warp & 1) * 128 + (lane >> 2) * 16;
    const int n0 = (warp >> 1) * 32 + (lane & 3) * 8;
    const int mpad = m0 + ((m0 >> 4) << 2);

    const int lr = tid >> 2;          // base row 0..63
    const int c4 = (tid & 3) * 4;     // k-offset 0,4,8,12

    const float* Ap = A  + (size_t)bm * K + kb;
    const float* Bp = Bm + (size_t)bn * K + kb;

    // Packed accumulators: accp[i2][j] lanes = rows (m0+2*i2, m0+2*i2+1), col j.
    unsigned long long accp[8][8];
#pragma unroll
    for (int i = 0; i < 8; i++)
#pragma unroll
        for (int j = 0; j < 8; j++) accp[i][j] = 0ull;

    const int NT = Kc / BK;
    float4 ar[4], br[2];

    // ---- prologue: global tile 0 -> smem buffer 0 ----
#pragma unroll
    for (int i = 0; i < 4; i++)
        ar[i] = *(const float4*)(Ap + (size_t)(lr + i * 64) * K + c4);
#pragma unroll
    for (int i = 0; i < 2; i++)
        br[i] = *(const float4*)(Bp + (size_t)(lr + i * 64) * K + c4);
#pragma unroll
    for (int i = 0; i < 4; i++) {
        const int r = lr + i * 64;
        Abase[AIDX(c4 + 0, r)] = ar[i].x; Abase[AIDX(c4 + 1, r)] = ar[i].y;
        Abase[AIDX(c4 + 2, r)] = ar[i].z; Abase[AIDX(c4 + 3, r)] = ar[i].w;
    }
#pragma unroll
    for (int i = 0; i < 2; i++) {
        const int r = lr + i * 64;
        Bs[0][c4 + 0][r] = br[i].x; Bs[0][c4 + 1][r] = br[i].y;
        Bs[0][c4 + 2][r] = br[i].z; Bs[0][c4 + 3][r] = br[i].w;
    }
    __syncthreads();

    for (int kt = 0; kt < NT; kt++) {
        const int cur = kt & 1;
        const float* Ab = Abase + cur * ABUF;

        // prefetch next global tile into registers (LDG hidden under compute)
        if (kt + 1 < NT) {
            const int k0 = (kt + 1) * BK;
#pragma unroll
            for (int i = 0; i < 4; i++)
                ar[i] = *(const float4*)(Ap + (size_t)(lr + i * 64) * K + k0 + c4);
#pragma unroll
            for (int i = 0; i < 2; i++)
                br[i] = *(const float4*)(Bp + (size_t)(lr + i * 64) * K + k0 + c4);
        }

        // compute: ascending k within the tile (per-lane chain order preserved)
#pragma unroll
        for (int k = 0; k < BK; k++) {
            // A fragment: 4x LDS.128; each float4 register quad already holds
            // two row-pairs as b64 lanes — no packing MOVs.
            union { float4 f; unsigned long long u[2]; } av[4];
#pragma unroll
            for (int i = 0; i < 4; i++)
                av[i].f = *(const float4*)&Ab[k * LDA + mpad + 4 * i];

            float b[8];
            *(float4*)(b)     = *(const float4*)&Bs[cur][k][n0];
            *(float4*)(b + 4) = *(const float4*)&Bs[cur][k][n0 + 4];
            unsigned long long bd[8];
#pragma unroll
            for (int j = 0; j < 8; j++)
                bd[j] = pack_dup(b[j]);

#pragma unroll
            for (int i2 = 0; i2 < 8; i2++) {
                const unsigned long long a2 = av[i2 >> 1].u[i2 & 1];
#pragma unroll
                for (int j = 0; j < 8; j++)
                    fma_f32x2(accp[i2][j], a2, bd[j]);
            }
        }

        if (kt + 1 < NT) {
            float* An = Abase + (cur ^ 1) * ABUF;
#pragma unroll
            for (int i = 0; i < 4; i++) {
                const int r = lr + i * 64;
                An[AIDX(c4 + 0, r)] = ar[i].x; An[AIDX(c4 + 1, r)] = ar[i].y;
                An[AIDX(c4 + 2, r)] = ar[i].z; An[AIDX(c4 + 3, r)] = ar[i].w;
            }
            const int nxt = cur ^ 1;
#pragma unroll
            for (int i = 0; i < 2; i++) {
                const int r = lr + i * 64;
                Bs[nxt][c4 + 0][r] = br[i].x; Bs[nxt][c4 + 1][r] = br[i].y;
                Bs[nxt][c4 + 2][r] = br[i].z; Bs[nxt][c4 + 3][r] = br[i].w;
            }
            __syncthreads();
        }
    }

    // epilogue: unpack row-pairs; store raw partials (reduce+bias in LIF)
    float* base = Part + (size_t)s * M * N + (size_t)(bm + m0) * N + bn + n0;
#pragma unroll
    for (int i2 = 0; i2 < 8; i2++) {
        float lo[8], hi[8];
#pragma unroll
        for (int j = 0; j < 8; j++)
            unpack2(accp[i2][j], lo[j], hi[j]);
        float* r0 = base + (size_t)(2 * i2) * N;
        float* r1 = base + (size_t)(2 * i2 + 1) * N;
        *(float4*)(r0)     = make_float4(lo[0], lo[1], lo[2], lo[3]);
        *(float4*)(r0 + 4) = make_float4(lo[4], lo[5], lo[6], lo[7]);
        *(float4*)(r1)     = make_float4(hi[0], hi[1], hi[2], hi[3]);
        *(float4*)(r1 + 4) = make_float4(hi[4], hi[5], hi[6], hi[7]);
    }
}

// ---------------------------------------------------------------------------
// LIF scans with fused split-K reduce + bias (rounding sequence unchanged).
// ---------------------------------------------------------------------------
__global__ void lif_scan1(const float* __restrict__ part,
                          const float* __restrict__ bias,
                          float* __restrict__ spk1)
{
    const int idx = blockIdx.x * blockDim.x + threadIdx.x;
    if (idx >= BB * NHID) return;
    const size_t stride  = (size_t)BB * NHID;
    const size_t pstride = (size_t)TT * BB * NHID;
    const float  bv = bias[idx % NHID];
    size_t off = idx;
    float mem = 0.0f;
#pragma unroll 4
    for (int t = 0; t < TT; t++) {
        float c = __fadd_rn(part[off], part[pstride + off]);
        c = __fadd_rn(c, bv);
        const float rst = (mem > THRESH) ? THRESH : 0.0f;
        float u = __fmul_rn(BETA, mem);
        u = __fadd_rn(u, c);
        mem = __fsub_rn(u, rst);
        spk1[off] = (mem > THRESH) ? 1.0f : 0.0f;
        off += stride;
    }
}

__global__ void lif_scan2(const float* __restrict__ part,
                          const float* __restrict__ bias,
                          float* __restrict__ out)
{
    const int idx = blockIdx.x * blockDim.x + threadIdx.x;
    if (idx >= BB * NOUT) return;
    const size_t stride  = (size_t)BB * NOUT;
    const size_t pstride = (size_t)TT * BB * NOUT;
    const size_t half    = (size_t)TT * BB * NOUT;
    const float  bv = bias[idx % NOUT];
    size_t off = idx;
    float mem = 0.0f;
    for (int t = 0; t < TT; t++) {
        float c = part[off];
#pragma unroll
        for (int s = 1; s < SPLIT2; s++)
            c = __fadd_rn(c, part[(size_t)s * pstride + off]);
        c = __fadd_rn(c, bv);
        const float rst = (mem > THRESH) ? THRESH : 0.0f;
        float u = __fmul_rn(BETA, mem);
        u = __fadd_rn(u, c);
        mem = __fsub_rn(u, rst);
        out[off]        = (mem > THRESH) ? 1.0f : 0.0f;  // spk_rec
        out[half + off] = mem;                           // mem_rec
        off += stride;
    }
}

// ---------------------------------------------------------------------------
// Launch
// ---------------------------------------------------------------------------
extern "C" void kernel_launch(void* const* d_in, const int* in_sizes, int n_in,
                              void* d_out, int out_size)
{
    const float* x  = (const float*)d_in[0];   // [T,B,NIN]
    const float* W1 = (const float*)d_in[1];   // [NHID,NIN]
    const float* b1 = (const float*)d_in[2];   // [NHID]
    const float* W2 = (const float*)d_in[3];   // [NOUT,NHID]
    const float* b2 = (const float*)d_in[4];   // [NOUT]
    float* out = (float*)d_out;

    float* spk1; cudaGetSymbolAddress((void**)&spk1, g_spk1);
    float* part; cudaGetSymbolAddress((void**)&part, g_part);

    cudaFuncSetAttribute(sgemm_nt_part,
                         cudaFuncAttributeMaxDynamicSharedMemorySize,
                         (int)GEMM_SMEM);

    const int M = TT * BB;  // 25600

    // GEMM1 partials: split-K = 2 over K=1024
    {
        dim3 grid(NHID / BN, M / BM, SPLIT1);
        sgemm_nt_part<<<grid, 256, GEMM_SMEM>>>(x, W1, part, M, NHID, NIN, NIN / SPLIT1);
    }

    // LIF scan layer 1 (fused split-K reduce + bias) -> spike train
    {
        const int n = BB * NHID;
        lif_scan1<<<(n + 255) / 256, 256>>>(part, b1, spk1);
    }

    // GEMM2 partials: split-K = 16 over K=4096
    {
        dim3 grid(NOUT / BN, M / BM, SPLIT2);
        sgemm_nt_part<<<grid, 256, GEMM_SMEM>>>(spk1, W2, part, M, NOUT, NHID, NHID / SPLIT2);
    }

    // LIF scan layer 2 (fused reduce + bias) -> d_out (spk_rec || mem_rec)
    {
        const int n = BB * NOUT;
        lif_scan2<<<(n + 255) / 256, 256>>>(part, b2, out);
    }
}